// round 8
// baseline (speedup 1.0000x reference)
#include <cuda_runtime.h>
#include <cstdint>

// Problem constants (fixed shapes from setup_inputs)
#define HDIM 512
#define WDIM 512
#define HW   (HDIM*WDIM)          // 262144 floats per plane
#define HS 54
#define PH 51                     // HS - WIN + 1
#define NPOS (PH*PH)              // 2601
#define CROP 64
#define STRIDE_I 8                // floor((512-70)/54)
#define RF_I 70

// Pipelined copy geometry
#define TILE_FLOATS 2048          // 8 KB tile
#define TILE_BYTES  (TILE_FLOATS*4)
#define TILES_PER_PLANE (HW / TILE_FLOATS)       // 128
#define COPY_TILES  (16 * 6 * TILES_PER_PLANE)   // 12288
#define NCOPY       768                          // persistent copy blocks
#define TPB         (COPY_TILES / NCOPY)         // 16 tiles per block (plane-uniform)
#define NBUF        3                            // ring buffers (lookahead 2)

#define CROP_BLOCKS (2 * 16 * 3 * CROP * CROP / 128)   // 3072 blocks of 128

// ---------------------------------------------------------------------------
__device__ __forceinline__ uint32_t smem_u32(const void* p) {
    return (uint32_t)__cvta_generic_to_shared(p);
}

__device__ __forceinline__ void bulk_load(uint32_t s_dst, const void* gsrc,
                                          uint32_t bytes, uint32_t s_bar) {
    asm volatile("mbarrier.arrive.expect_tx.shared.b64 _, [%0], %1;"
                 :: "r"(s_bar), "r"(bytes) : "memory");
    // NOTE: no cache hint -> evict_normal reads. realAB (100MB) stays
    // L2-resident across graph replays because stores are evict_first.
    asm volatile(
        "cp.async.bulk.shared::cluster.global.mbarrier::complete_tx::bytes "
        "[%0], [%1], %2, [%3];"
        :: "r"(s_dst), "l"(gsrc), "r"(bytes), "r"(s_bar)
        : "memory");
}

__device__ __forceinline__ void mbar_wait(uint32_t s_bar, uint32_t phase) {
    uint32_t done;
    asm volatile(
        "{\n\t.reg .pred p;\n\t"
        "mbarrier.try_wait.parity.acquire.cta.shared::cta.b64 p, [%1], %2;\n\t"
        "selp.b32 %0, 1, 0, p;\n\t}"
        : "=r"(done) : "r"(s_bar), "r"(phase) : "memory");
    if (!done) {
        asm volatile(
            "{\n\t.reg .pred P1;\n\t"
            "WL_%=:\n\t"
            "mbarrier.try_wait.parity.acquire.cta.shared::cta.b64 P1, [%0], %1, 0x989680;\n\t"
            "@P1 bra.uni WD_%=;\n\t"
            "bra.uni WL_%=;\n\t"
            "WD_%=:\n\t}"
            :: "r"(s_bar), "r"(phase) : "memory");
    }
}

// ---------------------------------------------------------------------------
// Block-local argmax over score_map[b,0,:51,:51] (first-occurrence tiebreak).
// All 128 threads participate; result broadcast via smem. Exactly matches the
// reference: argmax of flattened m[:51,:51], coords = idx/51, idx%51, gated
// on best > 0, then *8 + 70.
// ---------------------------------------------------------------------------
__shared__ float s_av[128];
__shared__ int   s_ai[128];
__shared__ int   s_axH, s_axW;

__device__ __forceinline__ void block_argmax(const float* __restrict__ score, int b) {
    int t = threadIdx.x;
    float best = -__int_as_float(0x7f800000);
    int bi = NPOS;
    for (int i = t; i < NPOS; i += 128) {
        int r = i / PH, c = i % PH;
        float v = score[b * (HS*HS) + r * HS + c];
        if (v > best) { best = v; bi = i; }   // increasing i => first occurrence
    }
    s_av[t] = best; s_ai[t] = bi;
    __syncthreads();
    for (int s = 64; s > 0; s >>= 1) {
        if (t < s) {
            float v2 = s_av[t + s]; int i2 = s_ai[t + s];
            if (v2 > s_av[t] || (v2 == s_av[t] && i2 < s_ai[t])) {
                s_av[t] = v2; s_ai[t] = i2;
            }
        }
        __syncthreads();
    }
    if (t == 0) {
        int idx  = s_ai[0];
        float bv = s_av[0];
        int x = (bv > 0.0f) ? (idx / PH) : 0;
        int y = (bv > 0.0f) ? (idx % PH) : 0;
        s_axH = x * STRIDE_I + RF_I;
        s_axW = y * STRIDE_I + RF_I;
    }
    __syncthreads();
}

// ---------------------------------------------------------------------------
// Single fused kernel: copy blocks [0, NCOPY) (persistent pipelined TMA),
// crop blocks after. Argmax computed redundantly per block (b is uniform).
// ---------------------------------------------------------------------------
__global__ __launch_bounds__(128) void fused_kernel(
        const float* __restrict__ realAB,
        const float* __restrict__ fakeAB,
        const float* __restrict__ score,
        const float* __restrict__ realB,
        const float* __restrict__ fakeB,
        float*       __restrict__ out_abm,
        float*       __restrict__ out_real,
        float*       __restrict__ out_fake)
{
    __shared__ __align__(16) float bufs[NBUF][TILE_FLOATS];
    __shared__ __align__(8)  uint64_t mbar[NBUF];

    if (blockIdx.x < NCOPY) {
        // ---------------- persistent pipelined TMA copy + patch ----------------
        int cb = blockIdx.x;
        int t0 = cb * TPB;                         // 16 tiles, all in one plane
        int plane = t0 / TILES_PER_PLANE;          // (b*6 + c), block-uniform
        int b = plane / 6;

        uint32_t s_bar0 = smem_u32(&mbar[0]);
        uint32_t s_buf0 = smem_u32(&bufs[0][0]);

        if (threadIdx.x == 0) {
            #pragma unroll
            for (int k = 0; k < NBUF; k++)
                asm volatile("mbarrier.init.shared.b64 [%0], 1;"
                             :: "r"(s_bar0 + k * 8) : "memory");
            asm volatile("fence.proxy.async.shared::cta;" ::: "memory");
            // prologue loads issued BEFORE argmax (hides argmax latency)
            #pragma unroll
            for (int k = 0; k < 2; k++)
                bulk_load(s_buf0 + k * TILE_BYTES,
                          realAB + (long long)(t0 + k) * TILE_FLOATS,
                          TILE_BYTES, s_bar0 + k * 8);
        }

        block_argmax(score, b);                    // all 128 threads
        int loffE = s_axH * WDIM + s_axW;          // plane-local patched element

        if (threadIdx.x != 0) return;              // orchestration is 1-thread

        uint64_t pol;
        asm volatile("createpolicy.fractional.L2::evict_first.b64 %0, 1.0;"
                     : "=l"(pol));

        for (int i = 0; i < TPB; i++) {
            int bi = i % NBUF;
            uint32_t ph = (uint32_t)((i / NBUF) & 1);
            mbar_wait(s_bar0 + bi * 8, ph);

            // patch: at most one element per tile
            int t  = t0 + i;
            int tp = t & (TILES_PER_PLANE - 1);
            int local = loffE - tp * TILE_FLOATS;
            if (local >= 0 && local < TILE_FLOATS)
                bufs[bi][local] = fakeAB[(long long)plane * HW + loffE];
            asm volatile("fence.proxy.async.shared::cta;" ::: "memory");

            // async bulk store (evict_first: keep L2 clean for next replay's reads)
            asm volatile(
                "cp.async.bulk.global.shared::cta.bulk_group.L2::cache_hint "
                "[%0], [%1], %2, %3;"
                :: "l"(out_abm + (long long)t * TILE_FLOATS),
                   "r"(s_buf0 + bi * TILE_BYTES), "r"((uint32_t)TILE_BYTES), "l"(pol)
                : "memory");
            asm volatile("cp.async.bulk.commit_group;" ::: "memory");

            // lookahead-2 load once store (i-1) drained
            if (i + 2 < TPB) {
                asm volatile("cp.async.bulk.wait_group 1;" ::: "memory");
                int j  = i + 2;
                int bj = j % NBUF;
                bulk_load(s_buf0 + bj * TILE_BYTES,
                          realAB + (long long)(t0 + j) * TILE_FLOATS,
                          TILE_BYTES, s_bar0 + bj * 8);
            }
        }
        asm volatile("cp.async.bulk.wait_group 0;" ::: "memory");
        return;
    }

    // ---------------- crop-and-resize (exact fp32 sequence) ----------------
    int gid = (blockIdx.x - NCOPY) * 128 + threadIdx.x;
    int per = 16 * 3 * CROP * CROP;
    int which = (gid >= per) ? 1 : 0;          // 0 = real, 1 = fake
    int lid = gid - which * per;

    int j = lid & (CROP - 1);
    int i = (lid >> 6) & (CROP - 1);
    int c = (lid >> 12) % 3;
    int b = lid / (3 * CROP * CROP);           // block-uniform (128 | 4096)

    block_argmax(score, b);                    // all 128 threads, b uniform
    float axH = (float)s_axH;
    float axW = (float)s_axW;

    const float* img = (which ? fakeB : realB) + ((long long)b * 3 + c) * HW;
    float* dst = which ? out_fake : out_real;

    float nh  = __fdiv_rn(63.0f, (float)(HDIM - 1));
    float ny0 = __fdiv_rn(axH, (float)(HDIM - 1));
    float nx0 = __fdiv_rn(axW, (float)(WDIM - 1));
    float ny1 = __fadd_rn(ny0, nh);
    float nx1 = __fadd_rn(nx0, nh);
    float dy  = __fsub_rn(ny1, ny0);
    float dx  = __fsub_rn(nx1, nx0);

    float ys = __fadd_rn(__fmul_rn(ny0, (float)(HDIM - 1)),
                         __fdiv_rn(__fmul_rn(__fmul_rn((float)i, dy), (float)(HDIM - 1)),
                                   (float)(CROP - 1)));
    float xs = __fadd_rn(__fmul_rn(nx0, (float)(WDIM - 1)),
                         __fdiv_rn(__fmul_rn(__fmul_rn((float)j, dx), (float)(WDIM - 1)),
                                   (float)(CROP - 1)));

    bool vy = (ys >= 0.0f) && (ys <= (float)(HDIM - 1));
    bool vx = (xs >= 0.0f) && (xs <= (float)(WDIM - 1));

    float y0f = floorf(ys);
    float x0f = floorf(xs);
    int y0 = (int)fminf(fmaxf(y0f, 0.0f), (float)(HDIM - 1));
    int x0 = (int)fminf(fmaxf(x0f, 0.0f), (float)(WDIM - 1));
    int y1 = min(y0 + 1, HDIM - 1);
    int x1 = min(x0 + 1, WDIM - 1);

    float ly = __fsub_rn(ys, y0f);
    float lx = __fsub_rn(xs, x0f);

    float v00 = img[(long long)y0 * WDIM + x0];
    float v01 = img[(long long)y0 * WDIM + x1];
    float v10 = img[(long long)y1 * WDIM + x0];
    float v11 = img[(long long)y1 * WDIM + x1];

    float one_lx = __fsub_rn(1.0f, lx);
    float one_ly = __fsub_rn(1.0f, ly);
    float top = __fadd_rn(__fmul_rn(one_lx, v00), __fmul_rn(lx, v01));
    float bot = __fadd_rn(__fmul_rn(one_lx, v10), __fmul_rn(lx, v11));
    float val = __fadd_rn(__fmul_rn(one_ly, top), __fmul_rn(ly, bot));

    dst[lid] = (vy && vx) ? val : 0.0f;
}

// ---------------------------------------------------------------------------
extern "C" void kernel_launch(void* const* d_in, const int* in_sizes, int n_in,
                              void* d_out, int out_size) {
    const float* real_AB   = (const float*)d_in[0];
    const float* fake_AB   = (const float*)d_in[1];
    const float* score_map = (const float*)d_in[2];
    const float* real_B    = (const float*)d_in[3];
    const float* fake_B    = (const float*)d_in[4];
    float* out = (float*)d_out;

    long long abm_elems  = (long long)16 * 6 * HW;             // 25,165,824
    long long crop_elems = (long long)16 * 3 * CROP * CROP;    // 196,608

    float* out_abm  = out;
    float* out_real = out + abm_elems;
    float* out_fake = out + abm_elems + crop_elems;

    // Single kernel: copy blocks first (all TMA streams start in wave 1),
    // crop blocks after. Argmax is computed per-block (no separate launch).
    fused_kernel<<<NCOPY + CROP_BLOCKS, 128>>>(
        real_AB, fake_AB, score_map, real_B, fake_B,
        out_abm, out_real, out_fake);
}

// round 9
// speedup vs baseline: 1.1560x; 1.1560x over previous
#include <cuda_runtime.h>
#include <cstdint>

// Problem constants (fixed shapes from setup_inputs)
#define HDIM 512
#define WDIM 512
#define HW   (HDIM*WDIM)          // 262144 floats per plane
#define HS 54
#define PH 51                     // HS - WIN + 1
#define NPOS (PH*PH)              // 2601
#define CROP 64
#define STRIDE_I 8                // floor((512-70)/54)
#define RF_I 70

// Pipelined copy geometry
#define TILE_FLOATS 2048          // 8 KB tile
#define TILE_BYTES  (TILE_FLOATS*4)
#define TILES_PER_PLANE (HW / TILE_FLOATS)       // 128
#define COPY_TILES  (16 * 6 * TILES_PER_PLANE)   // 12288
#define NCOPY       768                          // persistent copy blocks
#define TPB         (COPY_TILES / NCOPY)         // 16 tiles per block (plane-uniform)
#define NBUF        3                            // ring buffers (lookahead 2)

// Crop: one block per (which, b, c) plane; 4096 px / 128 threads = 32 px/thread
#define NCROP       (2 * 16 * 3)                 // 96

// ---------------------------------------------------------------------------
__device__ __forceinline__ uint32_t smem_u32(const void* p) {
    return (uint32_t)__cvta_generic_to_shared(p);
}

__device__ __forceinline__ void bulk_load(uint32_t s_dst, const void* gsrc,
                                          uint32_t bytes, uint32_t s_bar, uint64_t pol) {
    asm volatile("mbarrier.arrive.expect_tx.shared.b64 _, [%0], %1;"
                 :: "r"(s_bar), "r"(bytes) : "memory");
    asm volatile(
        "cp.async.bulk.shared::cluster.global.mbarrier::complete_tx::bytes"
        ".L2::cache_hint [%0], [%1], %2, [%3], %4;"
        :: "r"(s_dst), "l"(gsrc), "r"(bytes), "r"(s_bar), "l"(pol)
        : "memory");
}

__device__ __forceinline__ void mbar_wait(uint32_t s_bar, uint32_t phase) {
    uint32_t done;
    asm volatile(
        "{\n\t.reg .pred p;\n\t"
        "mbarrier.try_wait.parity.acquire.cta.shared::cta.b64 p, [%1], %2;\n\t"
        "selp.b32 %0, 1, 0, p;\n\t}"
        : "=r"(done) : "r"(s_bar), "r"(phase) : "memory");
    if (!done) {
        asm volatile(
            "{\n\t.reg .pred P1;\n\t"
            "WL_%=:\n\t"
            "mbarrier.try_wait.parity.acquire.cta.shared::cta.b64 P1, [%0], %1, 0x989680;\n\t"
            "@P1 bra.uni WD_%=;\n\t"
            "bra.uni WL_%=;\n\t"
            "WD_%=:\n\t}"
            :: "r"(s_bar), "r"(phase) : "memory");
    }
}

// ---------------------------------------------------------------------------
// Block-local argmax over score_map[b,0,:51,:51] (first-occurrence tiebreak).
// Exactly matches reference: argmax of flattened m[:51,:51], coords idx/51,
// idx%51, gated on best > 0, then *8 + 70.
// ---------------------------------------------------------------------------
__shared__ float s_av[128];
__shared__ int   s_ai[128];
__shared__ int   s_axH, s_axW;

__device__ __forceinline__ void block_argmax(const float* __restrict__ score, int b) {
    int t = threadIdx.x;
    float best = -__int_as_float(0x7f800000);
    int bi = NPOS;
    for (int i = t; i < NPOS; i += 128) {
        int r = i / PH, c = i % PH;
        float v = score[b * (HS*HS) + r * HS + c];
        if (v > best) { best = v; bi = i; }   // increasing i => first occurrence
    }
    s_av[t] = best; s_ai[t] = bi;
    __syncthreads();
    for (int s = 64; s > 0; s >>= 1) {
        if (t < s) {
            float v2 = s_av[t + s]; int i2 = s_ai[t + s];
            if (v2 > s_av[t] || (v2 == s_av[t] && i2 < s_ai[t])) {
                s_av[t] = v2; s_ai[t] = i2;
            }
        }
        __syncthreads();
    }
    if (t == 0) {
        int idx  = s_ai[0];
        float bv = s_av[0];
        int x = (bv > 0.0f) ? (idx / PH) : 0;
        int y = (bv > 0.0f) ? (idx % PH) : 0;
        s_axH = x * STRIDE_I + RF_I;
        s_axW = y * STRIDE_I + RF_I;
    }
    __syncthreads();
}

// ---------------------------------------------------------------------------
// Single fused kernel:
//   blocks [0, NCOPY):        persistent pipelined TMA copy + patch
//   blocks [NCOPY, +NCROP):   one crop plane each (32 px/thread)
// Argmax computed redundantly per block (b block-uniform everywhere).
// ---------------------------------------------------------------------------
__global__ __launch_bounds__(128) void fused_kernel(
        const float* __restrict__ realAB,
        const float* __restrict__ fakeAB,
        const float* __restrict__ score,
        const float* __restrict__ realB,
        const float* __restrict__ fakeB,
        float*       __restrict__ out_abm,
        float*       __restrict__ out_real,
        float*       __restrict__ out_fake)
{
    __shared__ __align__(16) float bufs[NBUF][TILE_FLOATS];
    __shared__ __align__(8)  uint64_t mbar[NBUF];

    if (blockIdx.x < NCOPY) {
        // ---------------- persistent pipelined TMA copy + patch ----------------
        int cb = blockIdx.x;
        int t0 = cb * TPB;                         // 16 tiles, all in one plane
        int plane = t0 / TILES_PER_PLANE;          // (b*6 + c), block-uniform
        int b = plane / 6;

        uint32_t s_bar0 = smem_u32(&mbar[0]);
        uint32_t s_buf0 = smem_u32(&bufs[0][0]);

        uint64_t pol;
        asm volatile("createpolicy.fractional.L2::evict_first.b64 %0, 1.0;"
                     : "=l"(pol));

        if (threadIdx.x == 0) {
            #pragma unroll
            for (int k = 0; k < NBUF; k++)
                asm volatile("mbarrier.init.shared.b64 [%0], 1;"
                             :: "r"(s_bar0 + k * 8) : "memory");
            asm volatile("fence.proxy.async.shared::cta;" ::: "memory");
            // prologue loads issued BEFORE argmax (argmax hides behind TMA)
            #pragma unroll
            for (int k = 0; k < 2; k++)
                bulk_load(s_buf0 + k * TILE_BYTES,
                          realAB + (long long)(t0 + k) * TILE_FLOATS,
                          TILE_BYTES, s_bar0 + k * 8, pol);
        }

        block_argmax(score, b);                    // all 128 threads
        int loffE = s_axH * WDIM + s_axW;          // plane-local patched element

        if (threadIdx.x != 0) return;              // orchestration is 1-thread

        for (int i = 0; i < TPB; i++) {
            int bi = i % NBUF;
            uint32_t ph = (uint32_t)((i / NBUF) & 1);
            mbar_wait(s_bar0 + bi * 8, ph);

            // patch: at most one element per tile
            int t  = t0 + i;
            int tp = t & (TILES_PER_PLANE - 1);
            int local = loffE - tp * TILE_FLOATS;
            if (local >= 0 && local < TILE_FLOATS)
                bufs[bi][local] = fakeAB[(long long)plane * HW + loffE];
            asm volatile("fence.proxy.async.shared::cta;" ::: "memory");

            // async bulk store (evict_first: keep the 200MB stream out of L2)
            asm volatile(
                "cp.async.bulk.global.shared::cta.bulk_group.L2::cache_hint "
                "[%0], [%1], %2, %3;"
                :: "l"(out_abm + (long long)t * TILE_FLOATS),
                   "r"(s_buf0 + bi * TILE_BYTES), "r"((uint32_t)TILE_BYTES), "l"(pol)
                : "memory");
            asm volatile("cp.async.bulk.commit_group;" ::: "memory");

            // lookahead-2 load once store (i-1) drained
            if (i + 2 < TPB) {
                asm volatile("cp.async.bulk.wait_group 1;" ::: "memory");
                int j  = i + 2;
                int bj = j % NBUF;
                bulk_load(s_buf0 + bj * TILE_BYTES,
                          realAB + (long long)(t0 + j) * TILE_FLOATS,
                          TILE_BYTES, s_bar0 + bj * 8, pol);
            }
        }
        asm volatile("cp.async.bulk.wait_group 0;" ::: "memory");
        return;
    }

    // ---------------- crop-and-resize: one plane per block ----------------
    int p = blockIdx.x - NCOPY;                // 0..95
    int which = p / 48;                        // 0 = real, 1 = fake
    int rem   = p - which * 48;
    int b     = rem / 3;
    int c     = rem - b * 3;

    block_argmax(score, b);                    // all 128 threads, b uniform
    float axH = (float)s_axH;
    float axW = (float)s_axW;

    const float* img = (which ? fakeB : realB) + ((long long)b * 3 + c) * HW;
    float* dst = (which ? out_fake : out_real) + ((long long)b * 3 + c) * (CROP * CROP);

    // box params (block-uniform, exact fp32 sequence)
    float nh  = __fdiv_rn(63.0f, (float)(HDIM - 1));
    float ny0 = __fdiv_rn(axH, (float)(HDIM - 1));
    float nx0 = __fdiv_rn(axW, (float)(WDIM - 1));
    float ny1 = __fadd_rn(ny0, nh);
    float nx1 = __fadd_rn(nx0, nh);
    float dy  = __fsub_rn(ny1, ny0);
    float dx  = __fsub_rn(nx1, nx0);
    float ybase = __fmul_rn(ny0, (float)(HDIM - 1));
    float xbase = __fmul_rn(nx0, (float)(WDIM - 1));

    for (int lid = threadIdx.x; lid < CROP * CROP; lid += 128) {
        int j = lid & (CROP - 1);
        int i = lid >> 6;

        float ys = __fadd_rn(ybase,
                             __fdiv_rn(__fmul_rn(__fmul_rn((float)i, dy), (float)(HDIM - 1)),
                                       (float)(CROP - 1)));
        float xs = __fadd_rn(xbase,
                             __fdiv_rn(__fmul_rn(__fmul_rn((float)j, dx), (float)(WDIM - 1)),
                                       (float)(CROP - 1)));

        bool vy = (ys >= 0.0f) && (ys <= (float)(HDIM - 1));
        bool vx = (xs >= 0.0f) && (xs <= (float)(WDIM - 1));

        float y0f = floorf(ys);
        float x0f = floorf(xs);
        int y0 = (int)fminf(fmaxf(y0f, 0.0f), (float)(HDIM - 1));
        int x0 = (int)fminf(fmaxf(x0f, 0.0f), (float)(WDIM - 1));
        int y1 = min(y0 + 1, HDIM - 1);
        int x1 = min(x0 + 1, WDIM - 1);

        float ly = __fsub_rn(ys, y0f);
        float lx = __fsub_rn(xs, x0f);

        float v00 = img[(long long)y0 * WDIM + x0];
        float v01 = img[(long long)y0 * WDIM + x1];
        float v10 = img[(long long)y1 * WDIM + x0];
        float v11 = img[(long long)y1 * WDIM + x1];

        float one_lx = __fsub_rn(1.0f, lx);
        float one_ly = __fsub_rn(1.0f, ly);
        float top = __fadd_rn(__fmul_rn(one_lx, v00), __fmul_rn(lx, v01));
        float bot = __fadd_rn(__fmul_rn(one_lx, v10), __fmul_rn(lx, v11));
        float val = __fadd_rn(__fmul_rn(one_ly, top), __fmul_rn(ly, bot));

        dst[lid] = (vy && vx) ? val : 0.0f;
    }
}

// ---------------------------------------------------------------------------
extern "C" void kernel_launch(void* const* d_in, const int* in_sizes, int n_in,
                              void* d_out, int out_size) {
    const float* real_AB   = (const float*)d_in[0];
    const float* fake_AB   = (const float*)d_in[1];
    const float* score_map = (const float*)d_in[2];
    const float* real_B    = (const float*)d_in[3];
    const float* fake_B    = (const float*)d_in[4];
    float* out = (float*)d_out;

    long long abm_elems  = (long long)16 * 6 * HW;             // 25,165,824
    long long crop_elems = (long long)16 * 3 * CROP * CROP;    // 196,608

    float* out_abm  = out;
    float* out_real = out + abm_elems;
    float* out_fake = out + abm_elems + crop_elems;

    // Single launch: copy blocks first (TMA streams start immediately),
    // 96 crop plane-blocks after (fully overlapped with the copy).
    fused_kernel<<<NCOPY + NCROP, 128>>>(
        real_AB, fake_AB, score_map, real_B, fake_B,
        out_abm, out_real, out_fake);
}

// round 10
// speedup vs baseline: 1.1683x; 1.0107x over previous
#include <cuda_runtime.h>
#include <cstdint>

// Problem constants (fixed shapes from setup_inputs)
#define HDIM 512
#define WDIM 512
#define HW   (HDIM*WDIM)          // 262144 floats per plane
#define HS 54
#define PH 51                     // HS - WIN + 1
#define NPOS (PH*PH)              // 2601
#define CROP 64
#define STRIDE_I 8                // floor((512-70)/54)
#define RF_I 70

// Pipelined copy geometry
#define TILE_FLOATS 2048          // 8 KB tile
#define TILE_BYTES  (TILE_FLOATS*4)
#define TILES_PER_PLANE (HW / TILE_FLOATS)       // 128
#define COPY_TILES  (16 * 6 * TILES_PER_PLANE)   // 12288
#define NCOPY       768                          // persistent copy blocks
#define TPB         (COPY_TILES / NCOPY)         // 16 tiles per block (plane-uniform)
#define NBUF        3                            // ring buffers (lookahead 2)

// Crop: 4 chunks per (which,b,c) plane; 1024 px/chunk, 8 px/thread unrolled
#define CROP_CHUNKS 4
#define NCROP       (2 * 16 * 3 * CROP_CHUNKS)   // 384
#define PX_PER_THREAD 8

// ---------------------------------------------------------------------------
__device__ __forceinline__ uint32_t smem_u32(const void* p) {
    return (uint32_t)__cvta_generic_to_shared(p);
}

__device__ __forceinline__ void bulk_load(uint32_t s_dst, const void* gsrc,
                                          uint32_t bytes, uint32_t s_bar, uint64_t pol) {
    asm volatile("mbarrier.arrive.expect_tx.shared.b64 _, [%0], %1;"
                 :: "r"(s_bar), "r"(bytes) : "memory");
    asm volatile(
        "cp.async.bulk.shared::cluster.global.mbarrier::complete_tx::bytes"
        ".L2::cache_hint [%0], [%1], %2, [%3], %4;"
        :: "r"(s_dst), "l"(gsrc), "r"(bytes), "r"(s_bar), "l"(pol)
        : "memory");
}

__device__ __forceinline__ void mbar_wait(uint32_t s_bar, uint32_t phase) {
    uint32_t done;
    asm volatile(
        "{\n\t.reg .pred p;\n\t"
        "mbarrier.try_wait.parity.acquire.cta.shared::cta.b64 p, [%1], %2;\n\t"
        "selp.b32 %0, 1, 0, p;\n\t}"
        : "=r"(done) : "r"(s_bar), "r"(phase) : "memory");
    if (!done) {
        asm volatile(
            "{\n\t.reg .pred P1;\n\t"
            "WL_%=:\n\t"
            "mbarrier.try_wait.parity.acquire.cta.shared::cta.b64 P1, [%0], %1, 0x989680;\n\t"
            "@P1 bra.uni WD_%=;\n\t"
            "bra.uni WL_%=;\n\t"
            "WD_%=:\n\t}"
            :: "r"(s_bar), "r"(phase) : "memory");
    }
}

// ---------------------------------------------------------------------------
// Block-local argmax over score_map[b,0,:51,:51] (first-occurrence tiebreak).
// ---------------------------------------------------------------------------
__shared__ float s_av[128];
__shared__ int   s_ai[128];
__shared__ int   s_axH, s_axW;

__device__ __forceinline__ void block_argmax(const float* __restrict__ score, int b) {
    int t = threadIdx.x;
    float best = -__int_as_float(0x7f800000);
    int bi = NPOS;
    for (int i = t; i < NPOS; i += 128) {
        int r = i / PH, c = i % PH;
        float v = score[b * (HS*HS) + r * HS + c];
        if (v > best) { best = v; bi = i; }   // increasing i => first occurrence
    }
    s_av[t] = best; s_ai[t] = bi;
    __syncthreads();
    for (int s = 64; s > 0; s >>= 1) {
        if (t < s) {
            float v2 = s_av[t + s]; int i2 = s_ai[t + s];
            if (v2 > s_av[t] || (v2 == s_av[t] && i2 < s_ai[t])) {
                s_av[t] = v2; s_ai[t] = i2;
            }
        }
        __syncthreads();
    }
    if (t == 0) {
        int idx  = s_ai[0];
        float bv = s_av[0];
        int x = (bv > 0.0f) ? (idx / PH) : 0;
        int y = (bv > 0.0f) ? (idx % PH) : 0;
        s_axH = x * STRIDE_I + RF_I;
        s_axW = y * STRIDE_I + RF_I;
    }
    __syncthreads();
}

// ---------------------------------------------------------------------------
// Single fused kernel:
//   blocks [0, NCOPY):        persistent pipelined TMA copy + patch
//   blocks [NCOPY, +NCROP):   crop chunks (1024 px each, 8 px/thread unrolled)
// ---------------------------------------------------------------------------
__global__ __launch_bounds__(128) void fused_kernel(
        const float* __restrict__ realAB,
        const float* __restrict__ fakeAB,
        const float* __restrict__ score,
        const float* __restrict__ realB,
        const float* __restrict__ fakeB,
        float*       __restrict__ out_abm,
        float*       __restrict__ out_real,
        float*       __restrict__ out_fake)
{
    __shared__ __align__(16) float bufs[NBUF][TILE_FLOATS];
    __shared__ __align__(8)  uint64_t mbar[NBUF];

    if (blockIdx.x < NCOPY) {
        // ---------------- persistent pipelined TMA copy + patch ----------------
        int cb = blockIdx.x;
        int t0 = cb * TPB;                         // 16 tiles, all in one plane
        int plane = t0 / TILES_PER_PLANE;          // (b*6 + c), block-uniform
        int b = plane / 6;

        uint32_t s_bar0 = smem_u32(&mbar[0]);
        uint32_t s_buf0 = smem_u32(&bufs[0][0]);

        uint64_t pol;
        asm volatile("createpolicy.fractional.L2::evict_first.b64 %0, 1.0;"
                     : "=l"(pol));

        if (threadIdx.x == 0) {
            #pragma unroll
            for (int k = 0; k < NBUF; k++)
                asm volatile("mbarrier.init.shared.b64 [%0], 1;"
                             :: "r"(s_bar0 + k * 8) : "memory");
            asm volatile("fence.proxy.async.shared::cta;" ::: "memory");
            // prologue loads issued BEFORE argmax (argmax hides behind TMA)
            #pragma unroll
            for (int k = 0; k < 2; k++)
                bulk_load(s_buf0 + k * TILE_BYTES,
                          realAB + (long long)(t0 + k) * TILE_FLOATS,
                          TILE_BYTES, s_bar0 + k * 8, pol);
        }

        block_argmax(score, b);                    // all 128 threads
        int loffE = s_axH * WDIM + s_axW;          // plane-local patched element

        if (threadIdx.x != 0) return;              // orchestration is 1-thread

        for (int i = 0; i < TPB; i++) {
            int bi = i % NBUF;
            uint32_t ph = (uint32_t)((i / NBUF) & 1);
            mbar_wait(s_bar0 + bi * 8, ph);

            // patch: at most one element per tile
            int t  = t0 + i;
            int tp = t & (TILES_PER_PLANE - 1);
            int local = loffE - tp * TILE_FLOATS;
            if (local >= 0 && local < TILE_FLOATS)
                bufs[bi][local] = fakeAB[(long long)plane * HW + loffE];
            asm volatile("fence.proxy.async.shared::cta;" ::: "memory");

            // async bulk store (evict_first: keep the 200MB stream out of L2)
            asm volatile(
                "cp.async.bulk.global.shared::cta.bulk_group.L2::cache_hint "
                "[%0], [%1], %2, %3;"
                :: "l"(out_abm + (long long)t * TILE_FLOATS),
                   "r"(s_buf0 + bi * TILE_BYTES), "r"((uint32_t)TILE_BYTES), "l"(pol)
                : "memory");
            asm volatile("cp.async.bulk.commit_group;" ::: "memory");

            // lookahead-2 load once store (i-1) drained
            if (i + 2 < TPB) {
                asm volatile("cp.async.bulk.wait_group 1;" ::: "memory");
                int j  = i + 2;
                int bj = j % NBUF;
                bulk_load(s_buf0 + bj * TILE_BYTES,
                          realAB + (long long)(t0 + j) * TILE_FLOATS,
                          TILE_BYTES, s_bar0 + bj * 8, pol);
            }
        }
        asm volatile("cp.async.bulk.wait_group 0;" ::: "memory");
        return;
    }

    // ---------------- crop-and-resize: 1024-px chunk per block ----------------
    int p = blockIdx.x - NCOPY;                // 0..383
    int plane = p >> 2;                        // (which*48 + b*3 + c)
    int chunk = p & 3;
    int which = plane / 48;                    // 0 = real, 1 = fake
    int rem   = plane - which * 48;
    int b     = rem / 3;
    int c     = rem - b * 3;

    block_argmax(score, b);                    // all 128 threads, b uniform
    float axH = (float)s_axH;
    float axW = (float)s_axW;

    const float* img = (which ? fakeB : realB) + ((long long)b * 3 + c) * HW;
    float* dst = (which ? out_fake : out_real) + ((long long)b * 3 + c) * (CROP * CROP);

    // box params (block-uniform, exact fp32 sequence)
    float nh  = __fdiv_rn(63.0f, (float)(HDIM - 1));
    float ny0 = __fdiv_rn(axH, (float)(HDIM - 1));
    float nx0 = __fdiv_rn(axW, (float)(WDIM - 1));
    float ny1 = __fadd_rn(ny0, nh);
    float nx1 = __fadd_rn(nx0, nh);
    float dy  = __fsub_rn(ny1, ny0);
    float dx  = __fsub_rn(nx1, nx0);
    float ybase = __fmul_rn(ny0, (float)(HDIM - 1));
    float xbase = __fmul_rn(nx0, (float)(WDIM - 1));

    int base = chunk * (CROP * CROP / CROP_CHUNKS);   // 1024-px chunk

    #pragma unroll
    for (int k = 0; k < PX_PER_THREAD; k++) {
        int lid = base + k * 128 + threadIdx.x;
        int j = lid & (CROP - 1);
        int i = lid >> 6;

        float ys = __fadd_rn(ybase,
                             __fdiv_rn(__fmul_rn(__fmul_rn((float)i, dy), (float)(HDIM - 1)),
                                       (float)(CROP - 1)));
        float xs = __fadd_rn(xbase,
                             __fdiv_rn(__fmul_rn(__fmul_rn((float)j, dx), (float)(WDIM - 1)),
                                       (float)(CROP - 1)));

        bool vy = (ys >= 0.0f) && (ys <= (float)(HDIM - 1));
        bool vx = (xs >= 0.0f) && (xs <= (float)(WDIM - 1));

        float y0f = floorf(ys);
        float x0f = floorf(xs);
        int y0 = (int)fminf(fmaxf(y0f, 0.0f), (float)(HDIM - 1));
        int x0 = (int)fminf(fmaxf(x0f, 0.0f), (float)(WDIM - 1));
        int y1 = min(y0 + 1, HDIM - 1);
        int x1 = min(x0 + 1, WDIM - 1);

        float ly = __fsub_rn(ys, y0f);
        float lx = __fsub_rn(xs, x0f);

        float v00 = img[(long long)y0 * WDIM + x0];
        float v01 = img[(long long)y0 * WDIM + x1];
        float v10 = img[(long long)y1 * WDIM + x0];
        float v11 = img[(long long)y1 * WDIM + x1];

        float one_lx = __fsub_rn(1.0f, lx);
        float one_ly = __fsub_rn(1.0f, ly);
        float top = __fadd_rn(__fmul_rn(one_lx, v00), __fmul_rn(lx, v01));
        float bot = __fadd_rn(__fmul_rn(one_lx, v10), __fmul_rn(lx, v11));
        float val = __fadd_rn(__fmul_rn(one_ly, top), __fmul_rn(ly, bot));

        dst[lid] = (vy && vx) ? val : 0.0f;
    }
}

// ---------------------------------------------------------------------------
extern "C" void kernel_launch(void* const* d_in, const int* in_sizes, int n_in,
                              void* d_out, int out_size) {
    const float* real_AB   = (const float*)d_in[0];
    const float* fake_AB   = (const float*)d_in[1];
    const float* score_map = (const float*)d_in[2];
    const float* real_B    = (const float*)d_in[3];
    const float* fake_B    = (const float*)d_in[4];
    float* out = (float*)d_out;

    long long abm_elems  = (long long)16 * 6 * HW;             // 25,165,824
    long long crop_elems = (long long)16 * 3 * CROP * CROP;    // 196,608

    float* out_abm  = out;
    float* out_real = out + abm_elems;
    float* out_fake = out + abm_elems + crop_elems;

    // Single launch: copy blocks first (TMA streams start immediately),
    // 384 crop chunk-blocks after (fully overlapped with the copy).
    fused_kernel<<<NCOPY + NCROP, 128>>>(
        real_AB, fake_AB, score_map, real_B, fake_B,
        out_abm, out_real, out_fake);
}

// round 11
// speedup vs baseline: 1.1770x; 1.0074x over previous
#include <cuda_runtime.h>
#include <cstdint>

// Problem constants (fixed shapes from setup_inputs)
#define HDIM 512
#define WDIM 512
#define HW   (HDIM*WDIM)          // 262144 floats per plane
#define HS 54
#define PH 51                     // HS - WIN + 1
#define NPOS (PH*PH)              // 2601
#define CROP 64
#define STRIDE_I 8                // floor((512-70)/54)
#define RF_I 70

// Pipelined copy geometry
#define TILE_FLOATS 2048          // 8 KB tile
#define TILE_BYTES  (TILE_FLOATS*4)
#define TILES_PER_PLANE (HW / TILE_FLOATS)       // 128
#define COPY_TILES  (16 * 6 * TILES_PER_PLANE)   // 12288
#define NCOPY       768                          // persistent copy blocks
#define TPB         (COPY_TILES / NCOPY)         // 16 tiles per block (plane-uniform)
#define NBUF        3                            // ring buffers (lookahead 2)

// Crop: 4 chunks per (which,b,c) plane; 1024 px/chunk, 8 px/thread unrolled
#define CROP_CHUNKS 4
#define NCROP       (2 * 16 * 3 * CROP_CHUNKS)   // 384
#define PX_PER_THREAD 8

// ---------------------------------------------------------------------------
__device__ __forceinline__ uint32_t smem_u32(const void* p) {
    return (uint32_t)__cvta_generic_to_shared(p);
}

__device__ __forceinline__ void bulk_load(uint32_t s_dst, const void* gsrc,
                                          uint32_t bytes, uint32_t s_bar, uint64_t pol) {
    asm volatile("mbarrier.arrive.expect_tx.shared.b64 _, [%0], %1;"
                 :: "r"(s_bar), "r"(bytes) : "memory");
    asm volatile(
        "cp.async.bulk.shared::cluster.global.mbarrier::complete_tx::bytes"
        ".L2::cache_hint [%0], [%1], %2, [%3], %4;"
        :: "r"(s_dst), "l"(gsrc), "r"(bytes), "r"(s_bar), "l"(pol)
        : "memory");
}

__device__ __forceinline__ void mbar_wait(uint32_t s_bar, uint32_t phase) {
    uint32_t done;
    asm volatile(
        "{\n\t.reg .pred p;\n\t"
        "mbarrier.try_wait.parity.acquire.cta.shared::cta.b64 p, [%1], %2;\n\t"
        "selp.b32 %0, 1, 0, p;\n\t}"
        : "=r"(done) : "r"(s_bar), "r"(phase) : "memory");
    if (!done) {
        asm volatile(
            "{\n\t.reg .pred P1;\n\t"
            "WL_%=:\n\t"
            "mbarrier.try_wait.parity.acquire.cta.shared::cta.b64 P1, [%0], %1, 0x989680;\n\t"
            "@P1 bra.uni WD_%=;\n\t"
            "bra.uni WL_%=;\n\t"
            "WD_%=:\n\t}"
            :: "r"(s_bar), "r"(phase) : "memory");
    }
}

// ---------------------------------------------------------------------------
// Block-local argmax over score_map[b,0,:51,:51] (first-occurrence tiebreak).
// ---------------------------------------------------------------------------
__shared__ float s_av[128];
__shared__ int   s_ai[128];
__shared__ int   s_axH, s_axW;

__device__ __forceinline__ void block_argmax(const float* __restrict__ score, int b) {
    int t = threadIdx.x;
    float best = -__int_as_float(0x7f800000);
    int bi = NPOS;
    for (int i = t; i < NPOS; i += 128) {
        int r = i / PH, c = i % PH;
        float v = score[b * (HS*HS) + r * HS + c];
        if (v > best) { best = v; bi = i; }   // increasing i => first occurrence
    }
    s_av[t] = best; s_ai[t] = bi;
    __syncthreads();
    for (int s = 64; s > 0; s >>= 1) {
        if (t < s) {
            float v2 = s_av[t + s]; int i2 = s_ai[t + s];
            if (v2 > s_av[t] || (v2 == s_av[t] && i2 < s_ai[t])) {
                s_av[t] = v2; s_ai[t] = i2;
            }
        }
        __syncthreads();
    }
    if (t == 0) {
        int idx  = s_ai[0];
        float bv = s_av[0];
        int x = (bv > 0.0f) ? (idx / PH) : 0;
        int y = (bv > 0.0f) ? (idx % PH) : 0;
        s_axH = x * STRIDE_I + RF_I;
        s_axW = y * STRIDE_I + RF_I;
    }
    __syncthreads();
}

// ---------------------------------------------------------------------------
// Single fused kernel:
//   blocks [0, NCOPY):        persistent pipelined TMA copy + patch
//   blocks [NCOPY, +NCROP):   crop chunks (1024 px each, 8 px/thread unrolled)
// ---------------------------------------------------------------------------
__global__ __launch_bounds__(128) void fused_kernel(
        const float* __restrict__ realAB,
        const float* __restrict__ fakeAB,
        const float* __restrict__ score,
        const float* __restrict__ realB,
        const float* __restrict__ fakeB,
        float*       __restrict__ out_abm,
        float*       __restrict__ out_real,
        float*       __restrict__ out_fake)
{
    __shared__ __align__(16) float bufs[NBUF][TILE_FLOATS];
    __shared__ __align__(8)  uint64_t mbar[NBUF];

    if (blockIdx.x < NCOPY) {
        // ---------------- persistent pipelined TMA copy + patch ----------------
        int cb = blockIdx.x;
        int t0 = cb * TPB;                         // 16 tiles, all in one plane
        int plane = t0 / TILES_PER_PLANE;          // (b*6 + c), block-uniform
        int b = plane / 6;

        uint32_t s_bar0 = smem_u32(&mbar[0]);
        uint32_t s_buf0 = smem_u32(&bufs[0][0]);

        uint64_t pol;
        asm volatile("createpolicy.fractional.L2::evict_first.b64 %0, 1.0;"
                     : "=l"(pol));

        if (threadIdx.x == 0) {
            #pragma unroll
            for (int k = 0; k < NBUF; k++)
                asm volatile("mbarrier.init.shared.b64 [%0], 1;"
                             :: "r"(s_bar0 + k * 8) : "memory");
            asm volatile("fence.proxy.async.shared::cta;" ::: "memory");
            // prologue loads issued BEFORE argmax (argmax hides behind TMA)
            #pragma unroll
            for (int k = 0; k < 2; k++)
                bulk_load(s_buf0 + k * TILE_BYTES,
                          realAB + (long long)(t0 + k) * TILE_FLOATS,
                          TILE_BYTES, s_bar0 + k * 8, pol);
        }

        block_argmax(score, b);                    // all 128 threads
        int loffE = s_axH * WDIM + s_axW;          // plane-local patched element

        if (threadIdx.x != 0) return;              // orchestration is 1-thread

        for (int i = 0; i < TPB; i++) {
            int bi = i % NBUF;
            uint32_t ph = (uint32_t)((i / NBUF) & 1);
            mbar_wait(s_bar0 + bi * 8, ph);

            // patch: at most one element per tile
            int t  = t0 + i;
            int tp = t & (TILES_PER_PLANE - 1);
            int local = loffE - tp * TILE_FLOATS;
            if (local >= 0 && local < TILE_FLOATS)
                bufs[bi][local] = fakeAB[(long long)plane * HW + loffE];
            asm volatile("fence.proxy.async.shared::cta;" ::: "memory");

            // async bulk store (evict_first: keep the 200MB stream out of L2)
            asm volatile(
                "cp.async.bulk.global.shared::cta.bulk_group.L2::cache_hint "
                "[%0], [%1], %2, %3;"
                :: "l"(out_abm + (long long)t * TILE_FLOATS),
                   "r"(s_buf0 + bi * TILE_BYTES), "r"((uint32_t)TILE_BYTES), "l"(pol)
                : "memory");
            asm volatile("cp.async.bulk.commit_group;" ::: "memory");

            // lookahead-2 load once store (i-1) drained
            if (i + 2 < TPB) {
                asm volatile("cp.async.bulk.wait_group 1;" ::: "memory");
                int j  = i + 2;
                int bj = j % NBUF;
                bulk_load(s_buf0 + bj * TILE_BYTES,
                          realAB + (long long)(t0 + j) * TILE_FLOATS,
                          TILE_BYTES, s_bar0 + bj * 8, pol);
            }
        }
        asm volatile("cp.async.bulk.wait_group 0;" ::: "memory");
        return;
    }

    // ---------------- crop-and-resize: 1024-px chunk per block ----------------
    int p = blockIdx.x - NCOPY;                // 0..383
    int plane = p >> 2;                        // (which*48 + b*3 + c)
    int chunk = p & 3;
    int which = plane / 48;                    // 0 = real, 1 = fake
    int rem   = plane - which * 48;
    int b     = rem / 3;
    int c     = rem - b * 3;

    block_argmax(score, b);                    // all 128 threads, b uniform
    float axH = (float)s_axH;
    float axW = (float)s_axW;

    const float* img = (which ? fakeB : realB) + ((long long)b * 3 + c) * HW;
    float* dst = (which ? out_fake : out_real) + ((long long)b * 3 + c) * (CROP * CROP);

    // box params (block-uniform, exact fp32 sequence)
    float nh  = __fdiv_rn(63.0f, (float)(HDIM - 1));
    float ny0 = __fdiv_rn(axH, (float)(HDIM - 1));
    float nx0 = __fdiv_rn(axW, (float)(WDIM - 1));
    float ny1 = __fadd_rn(ny0, nh);
    float nx1 = __fadd_rn(nx0, nh);
    float dy  = __fsub_rn(ny1, ny0);
    float dx  = __fsub_rn(nx1, nx0);
    float ybase = __fmul_rn(ny0, (float)(HDIM - 1));
    float xbase = __fmul_rn(nx0, (float)(WDIM - 1));

    int base = chunk * (CROP * CROP / CROP_CHUNKS);   // 1024-px chunk

    #pragma unroll
    for (int k = 0; k < PX_PER_THREAD; k++) {
        int lid = base + k * 128 + threadIdx.x;
        int j = lid & (CROP - 1);
        int i = lid >> 6;

        float ys = __fadd_rn(ybase,
                             __fdiv_rn(__fmul_rn(__fmul_rn((float)i, dy), (float)(HDIM - 1)),
                                       (float)(CROP - 1)));
        float xs = __fadd_rn(xbase,
                             __fdiv_rn(__fmul_rn(__fmul_rn((float)j, dx), (float)(WDIM - 1)),
                                       (float)(CROP - 1)));

        bool vy = (ys >= 0.0f) && (ys <= (float)(HDIM - 1));
        bool vx = (xs >= 0.0f) && (xs <= (float)(WDIM - 1));

        float y0f = floorf(ys);
        float x0f = floorf(xs);
        int y0 = (int)fminf(fmaxf(y0f, 0.0f), (float)(HDIM - 1));
        int x0 = (int)fminf(fmaxf(x0f, 0.0f), (float)(WDIM - 1));
        int y1 = min(y0 + 1, HDIM - 1);
        int x1 = min(x0 + 1, WDIM - 1);

        float ly = __fsub_rn(ys, y0f);
        float lx = __fsub_rn(xs, x0f);

        float v00 = img[(long long)y0 * WDIM + x0];
        float v01 = img[(long long)y0 * WDIM + x1];
        float v10 = img[(long long)y1 * WDIM + x0];
        float v11 = img[(long long)y1 * WDIM + x1];

        float one_lx = __fsub_rn(1.0f, lx);
        float one_ly = __fsub_rn(1.0f, ly);
        float top = __fadd_rn(__fmul_rn(one_lx, v00), __fmul_rn(lx, v01));
        float bot = __fadd_rn(__fmul_rn(one_lx, v10), __fmul_rn(lx, v11));
        float val = __fadd_rn(__fmul_rn(one_ly, top), __fmul_rn(ly, bot));

        dst[lid] = (vy && vx) ? val : 0.0f;
    }
}

// ---------------------------------------------------------------------------
extern "C" void kernel_launch(void* const* d_in, const int* in_sizes, int n_in,
                              void* d_out, int out_size) {
    const float* real_AB   = (const float*)d_in[0];
    const float* fake_AB   = (const float*)d_in[1];
    const float* score_map = (const float*)d_in[2];
    const float* real_B    = (const float*)d_in[3];
    const float* fake_B    = (const float*)d_in[4];
    float* out = (float*)d_out;

    long long abm_elems  = (long long)16 * 6 * HW;             // 25,165,824
    long long crop_elems = (long long)16 * 3 * CROP * CROP;    // 196,608

    float* out_abm  = out;
    float* out_real = out + abm_elems;
    float* out_fake = out + abm_elems + crop_elems;

    // Single launch: copy blocks first (TMA streams start immediately),
    // 384 crop chunk-blocks after (fully overlapped with the copy).
    fused_kernel<<<NCOPY + NCROP, 128>>>(
        real_AB, fake_AB, score_map, real_B, fake_B,
        out_abm, out_real, out_fake);
}